// round 15
// baseline (speedup 1.0000x reference)
#include <cuda_runtime.h>
#include <cuda_bf16.h>

// ProjectBEV: input (B=16, H=64, W=2048, CK=3, 2) float32.
// Flattened element order (B, CK, H, W); N = 6,291,456.
// Output (float32, concatenated):
//   [0   , 6N )  presence_indices rows [b, qx, qy, c, h, w]
//   [6N  , 7N )  presence_vals (all 1)
//   [7N  , 21N)  position_indices rows [b, qx, qy, c, h, w, d], d=0,1
//   [21N , 23N)  position_vals [sx, sy]
// sx = 2x+1, sy = 2y+81, qx = trunc(sx), qy = trunc(sy).
//
// R15 = R14 (two roles: position_indices | presence_indices+both vals,
// warp-cooperative lane-contiguous STG.128) with 512-thread blocks owning
// 512 consecutive pairs: each block's store stream is 57KB/38KB contiguous
// (2x R14) for longer same-page DRAM bursts. Per-warp code identical.

__global__ __launch_bounds__(512)
void project_bev_kernel(const float* __restrict__ in,
                        float* __restrict__ out,
                        long N)
{
    const int  role = (int)(blockIdx.x & 1);   // 0=presence+vals, 1=position
    const long span = (long)(blockIdx.x >> 1); // 512 pairs per span
    const int  tid  = threadIdx.x;
    const int  lane = tid & 31;

    // ---- this thread's pair ----
    const long P  = span * 512 + tid;
    const long i0 = P << 1;
    const int w0 = (int)(i0 & 2047);
    const int h  = (int)((i0 >> 11) & 63);
    const int hi = (int)(i0 >> 17);            // b*3 + c
    const int b  = hi / 3;
    const int c  = hi - 3 * b;

    // input offset in float2 units: (((b*64+h)*2048 + w0)*3 + c)
    const long in_off = ((long)((b * 64 + h) * 2048 + w0)) * 3 + c;
    const float2 e0 = __ldg(((const float2*)in) + in_off);
    const float2 e1 = __ldg(((const float2*)in) + in_off + 3);

    const float sx0 = e0.x * 2.0f + 1.0f;
    const float sy0 = e0.y * 2.0f + 81.0f;
    const float sx1 = e1.x * 2.0f + 1.0f;
    const float sy1 = e1.y * 2.0f + 81.0f;

    const float qx0 = (float)(int)sx0;   // positive -> trunc == astype(int64)
    const float qy0 = (float)(int)sy0;
    const float qx1 = (float)(int)sx1;
    const float qy1 = (float)(int)sy1;
    const float bf = (float)b;           // warp-uniform
    const float cf = (float)c;           // warp-uniform
    const float hf = (float)h;           // warp-uniform

    const long  pairbase = span * 512 + (long)(tid & ~31);    // warp's first pair
    const float wbase = (float)(int)((pairbase << 1) & 2047); // warp-uniform

    if (role == 1) {
        // ---- position_indices: 7 float4 per pair, warp-cooperative ----
        float4* base4 = (float4*)(out + 7 * N) + 7 * pairbase;
#pragma unroll
        for (int m = 0; m < 7; m++) {
            const int j = 32 * m + lane;
            const int p = j / 7;
            const int k = j - 7 * p;
            const float X0 = __shfl_sync(0xffffffffu, qx0, p);
            const float Y0 = __shfl_sync(0xffffffffu, qy0, p);
            const float X1 = __shfl_sync(0xffffffffu, qx1, p);
            const float Y1 = __shfl_sync(0xffffffffu, qy1, p);
            const float W0 = wbase + 2.0f * (float)p;
            const float W1 = W0 + 1.0f;
            // word k of [b,qx0,qy0,c | h,w0,0,b | qx0,qy0,c,h | w0,1,b,qx1 |
            //            qy1,c,h,w1 | 0,b,qx1,qy1 | c,h,w1,1]
            const float c0 = k==0?bf : k==1?hf  : k==2?X0 : k==3?W0   : k==4?Y1 : k==5?0.0f : cf;
            const float c1 = k==0?X0 : k==1?W0  : k==2?Y0 : k==3?1.0f : k==4?cf : k==5?bf   : hf;
            const float c2 = k==0?Y0 : k==1?0.0f: k==2?cf : k==3?bf   : k==4?hf : k==5?X1   : W1;
            const float c3 = k==0?cf : k==1?bf  : k==2?hf : k==3?X1   : k==4?W1 : k==5?Y1   : 1.0f;
            __stcs(base4 + j, make_float4(c0, c1, c2, c3));
        }
    } else {
        // ---- position_vals: lane-contiguous float4 per pair ----
        __stcs((float4*)(out + 21 * N + 4 * P), make_float4(sx0, sy0, sx1, sy1));

        // ---- presence_vals: 1024 floats per span ----
        if (tid < 256)
            __stcs((float4*)(out + 6 * N + span * 1024) + tid,
                   make_float4(1.0f, 1.0f, 1.0f, 1.0f));

        // ---- presence_indices: 3 float4 per pair, warp-cooperative ----
        float4* base4 = (float4*)out + 3 * pairbase;
#pragma unroll
        for (int m = 0; m < 3; m++) {
            const int j = 32 * m + lane;
            const int p = j / 3;
            const int k = j - 3 * p;
            const float X0 = __shfl_sync(0xffffffffu, qx0, p);
            const float Y0 = __shfl_sync(0xffffffffu, qy0, p);
            const float X1 = __shfl_sync(0xffffffffu, qx1, p);
            const float Y1 = __shfl_sync(0xffffffffu, qy1, p);
            const float W0 = wbase + 2.0f * (float)p;
            const float W1 = W0 + 1.0f;
            // word k of [b,qx0,qy0,c | h,w0,b,qx1 | qy1,c,h,w1]
            const float c0 = k==0?bf : k==1?hf : Y1;
            const float c1 = k==0?X0 : k==1?W0 : cf;
            const float c2 = k==0?Y0 : k==1?bf : hf;
            const float c3 = k==0?cf : k==1?X1 : W1;
            __stcs(base4 + j, make_float4(c0, c1, c2, c3));
        }
    }
}

extern "C" void kernel_launch(void* const* d_in, const int* in_sizes, int n_in,
                              void* d_out, int out_size)
{
    const float* in = (const float*)d_in[0];
    float* out = (float*)d_out;

    const long N = (long)in_sizes[0] / 2;        // number of (x,y) points
    const long spans = N / 1024;                 // 512 pairs per span (exact)
    const int  blocks = (int)(spans * 2);        // 2 roles per span

    project_bev_kernel<<<blocks, 512>>>(in, out, N);
}

// round 16
// speedup vs baseline: 1.0078x; 1.0078x over previous
#include <cuda_runtime.h>
#include <cuda_bf16.h>

// ProjectBEV: input (B=16, H=64, W=2048, CK=3, 2) float32.
// Flattened element order (B, CK, H, W); N = 6,291,456.
// Output (float32, concatenated):
//   [0   , 6N )  presence_indices rows [b, qx, qy, c, h, w]
//   [6N  , 7N )  presence_vals (all 1)
//   [7N  , 21N)  position_indices rows [b, qx, qy, c, h, w, d], d=0,1
//   [21N , 23N)  position_vals [sx, sy]
// sx = 2x+1, sy = 2y+81, qx = trunc(sx), qy = trunc(sy).
//
// R15 = R14 (two roles: position_indices | presence_indices+both vals,
// warp-cooperative lane-contiguous STG.128) with 512-thread blocks owning
// 512 consecutive pairs: each block's store stream is 57KB/38KB contiguous
// (2x R14) for longer same-page DRAM bursts. Per-warp code identical.

__global__ __launch_bounds__(512)
void project_bev_kernel(const float* __restrict__ in,
                        float* __restrict__ out,
                        long N)
{
    const int  role = (int)(blockIdx.x & 1);   // 0=presence+vals, 1=position
    const long span = (long)(blockIdx.x >> 1); // 512 pairs per span
    const int  tid  = threadIdx.x;
    const int  lane = tid & 31;

    // ---- this thread's pair ----
    const long P  = span * 512 + tid;
    const long i0 = P << 1;
    const int w0 = (int)(i0 & 2047);
    const int h  = (int)((i0 >> 11) & 63);
    const int hi = (int)(i0 >> 17);            // b*3 + c
    const int b  = hi / 3;
    const int c  = hi - 3 * b;

    // input offset in float2 units: (((b*64+h)*2048 + w0)*3 + c)
    const long in_off = ((long)((b * 64 + h) * 2048 + w0)) * 3 + c;
    const float2 e0 = __ldg(((const float2*)in) + in_off);
    const float2 e1 = __ldg(((const float2*)in) + in_off + 3);

    const float sx0 = e0.x * 2.0f + 1.0f;
    const float sy0 = e0.y * 2.0f + 81.0f;
    const float sx1 = e1.x * 2.0f + 1.0f;
    const float sy1 = e1.y * 2.0f + 81.0f;

    const float qx0 = (float)(int)sx0;   // positive -> trunc == astype(int64)
    const float qy0 = (float)(int)sy0;
    const float qx1 = (float)(int)sx1;
    const float qy1 = (float)(int)sy1;
    const float bf = (float)b;           // warp-uniform
    const float cf = (float)c;           // warp-uniform
    const float hf = (float)h;           // warp-uniform

    const long  pairbase = span * 512 + (long)(tid & ~31);    // warp's first pair
    const float wbase = (float)(int)((pairbase << 1) & 2047); // warp-uniform

    if (role == 1) {
        // ---- position_indices: 7 float4 per pair, warp-cooperative ----
        float4* base4 = (float4*)(out + 7 * N) + 7 * pairbase;
#pragma unroll
        for (int m = 0; m < 7; m++) {
            const int j = 32 * m + lane;
            const int p = j / 7;
            const int k = j - 7 * p;
            const float X0 = __shfl_sync(0xffffffffu, qx0, p);
            const float Y0 = __shfl_sync(0xffffffffu, qy0, p);
            const float X1 = __shfl_sync(0xffffffffu, qx1, p);
            const float Y1 = __shfl_sync(0xffffffffu, qy1, p);
            const float W0 = wbase + 2.0f * (float)p;
            const float W1 = W0 + 1.0f;
            // word k of [b,qx0,qy0,c | h,w0,0,b | qx0,qy0,c,h | w0,1,b,qx1 |
            //            qy1,c,h,w1 | 0,b,qx1,qy1 | c,h,w1,1]
            const float c0 = k==0?bf : k==1?hf  : k==2?X0 : k==3?W0   : k==4?Y1 : k==5?0.0f : cf;
            const float c1 = k==0?X0 : k==1?W0  : k==2?Y0 : k==3?1.0f : k==4?cf : k==5?bf   : hf;
            const float c2 = k==0?Y0 : k==1?0.0f: k==2?cf : k==3?bf   : k==4?hf : k==5?X1   : W1;
            const float c3 = k==0?cf : k==1?bf  : k==2?hf : k==3?X1   : k==4?W1 : k==5?Y1   : 1.0f;
            __stcs(base4 + j, make_float4(c0, c1, c2, c3));
        }
    } else {
        // ---- position_vals: lane-contiguous float4 per pair ----
        __stcs((float4*)(out + 21 * N + 4 * P), make_float4(sx0, sy0, sx1, sy1));

        // ---- presence_vals: 1024 floats per span ----
        if (tid < 256)
            __stcs((float4*)(out + 6 * N + span * 1024) + tid,
                   make_float4(1.0f, 1.0f, 1.0f, 1.0f));

        // ---- presence_indices: 3 float4 per pair, warp-cooperative ----
        float4* base4 = (float4*)out + 3 * pairbase;
#pragma unroll
        for (int m = 0; m < 3; m++) {
            const int j = 32 * m + lane;
            const int p = j / 3;
            const int k = j - 3 * p;
            const float X0 = __shfl_sync(0xffffffffu, qx0, p);
            const float Y0 = __shfl_sync(0xffffffffu, qy0, p);
            const float X1 = __shfl_sync(0xffffffffu, qx1, p);
            const float Y1 = __shfl_sync(0xffffffffu, qy1, p);
            const float W0 = wbase + 2.0f * (float)p;
            const float W1 = W0 + 1.0f;
            // word k of [b,qx0,qy0,c | h,w0,b,qx1 | qy1,c,h,w1]
            const float c0 = k==0?bf : k==1?hf : Y1;
            const float c1 = k==0?X0 : k==1?W0 : cf;
            const float c2 = k==0?Y0 : k==1?bf : hf;
            const float c3 = k==0?cf : k==1?X1 : W1;
            __stcs(base4 + j, make_float4(c0, c1, c2, c3));
        }
    }
}

extern "C" void kernel_launch(void* const* d_in, const int* in_sizes, int n_in,
                              void* d_out, int out_size)
{
    const float* in = (const float*)d_in[0];
    float* out = (float*)d_out;

    const long N = (long)in_sizes[0] / 2;        // number of (x,y) points
    const long spans = N / 1024;                 // 512 pairs per span (exact)
    const int  blocks = (int)(spans * 2);        // 2 roles per span

    project_bev_kernel<<<blocks, 512>>>(in, out, N);
}